// round 1
// baseline (speedup 1.0000x reference)
#include <cuda_runtime.h>

#define DD 64
#define HH 512
#define WW 512
#define RR 4
#define KK 9
#define THRESH 0.5f

// 64 MB scratch for the W+H pooled volume (allocation-free rule: device global)
__device__ float g_tmp[(size_t)DD * HH * WW];

#define TW 256   // W tile = blockDim.x
#define TH 64    // H rows produced per block

// Kernel 1: threshold + 9-tap max along W (smem) + 9-tap max along H (register ring)
// grid: (WW/TW, HH/TH, DD), block: TW threads
__global__ void __launch_bounds__(TW) k_wh(const float* __restrict__ in) {
    __shared__ float srow[2][TW + 2 * RR + 8];  // 264 used + pad
    const int t  = threadIdx.x;
    const int w0 = blockIdx.x * TW;
    const int h0 = blockIdx.y * TH;
    const int d  = blockIdx.z;
    const float* base = in + (size_t)d * HH * WW;
    float* tmpb = g_tmp + (size_t)d * HH * WW;

    float ring[KK];
#pragma unroll
    for (int i = 0; i < KK; i++) ring[i] = 0.f;

    int buf = 0;
    for (int hi = h0 - RR; hi <= h0 + TH - 1 + RR; hi++) {
        // load thresholded row hi into srow[buf] (positions map w = w0-RR+idx)
        {
            float v = 0.f;
            int w = w0 - RR + t;
            if (hi >= 0 && hi < HH && w >= 0 && w < WW) {
                float x = base[(size_t)hi * WW + w];
                v = (x > THRESH) ? x : 0.f;
            }
            srow[buf][t] = v;
            if (t < 2 * RR) {
                float v2 = 0.f;
                int w2 = w0 - RR + TW + t;   // always >= TW-RR > 0
                if (hi >= 0 && hi < HH && w2 < WW) {
                    float x = base[(size_t)hi * WW + w2];
                    v2 = (x > THRESH) ? x : 0.f;
                }
                srow[buf][TW + t] = v2;
            }
        }
        __syncthreads();

        // 9-tap max along W for output column w0+t
        float m = srow[buf][t];
#pragma unroll
        for (int i = 1; i < KK; i++) m = fmaxf(m, srow[buf][t + i]);

        // push into H ring
#pragma unroll
        for (int i = 0; i < KK - 1; i++) ring[i] = ring[i + 1];
        ring[KK - 1] = m;

        int ho = hi - RR;
        if (ho >= h0) {
            float cm = ring[0];
#pragma unroll
            for (int i = 1; i < KK; i++) cm = fmaxf(cm, ring[i]);
            tmpb[(size_t)ho * WW + (w0 + t)] = cm;
        }
        buf ^= 1;   // double buffer: single sync per iteration is safe
    }
}

// Kernel 2: 9-tap max along D (register ring) + strict-local-max finalize
// grid: (WW/256, HH), block: 256 threads, each thread owns one (h,w) column
__global__ void __launch_bounds__(256) k_d(const float* __restrict__ in,
                                           float* __restrict__ out) {
    const int w = blockIdx.x * 256 + threadIdx.x;
    const int h = blockIdx.y;
    const size_t hw = (size_t)h * WW + w;
    const size_t slice = (size_t)HH * WW;

    float ring[KK];
#pragma unroll
    for (int i = 0; i < KK; i++) ring[i] = 0.f;

#pragma unroll 4
    for (int di = 0; di < DD + RR; di++) {
        float v = 0.f;
        if (di < DD) v = g_tmp[(size_t)di * slice + hw];
#pragma unroll
        for (int i = 0; i < KK - 1; i++) ring[i] = ring[i + 1];
        ring[KK - 1] = v;

        int dd = di - RR;
        if (dd >= 0) {
            float cm = ring[0];
#pragma unroll
            for (int i = 1; i < KK; i++) cm = fmaxf(cm, ring[i]);
            float x = in[(size_t)dd * slice + hw];
            float pt = (x > THRESH) ? x : 0.f;
            out[(size_t)dd * slice + hw] = (cm > 0.f && cm == pt) ? cm : 0.f;
        }
    }
}

extern "C" void kernel_launch(void* const* d_in, const int* in_sizes, int n_in,
                              void* d_out, int out_size) {
    const float* in = (const float*)d_in[0];
    float* out = (float*)d_out;

    dim3 g1(WW / TW, HH / TH, DD);   // (2, 8, 64)
    k_wh<<<g1, TW>>>(in);

    dim3 g2(WW / 256, HH);           // (2, 512)
    k_d<<<g2, 256>>>(in, out);
}

// round 3
// speedup vs baseline: 1.2102x; 1.2102x over previous
#include <cuda_runtime.h>

#define DD 64
#define HH 512
#define WW 512
#define W4 (WW / 4)
#define THRESH 0.5f

// 64 MB scratch (device global per allocation-free rule): W+H pooled volume
__device__ float4 g_tmp[(size_t)DD * HH * W4];

#define TH1 64  // H rows produced per block in k1

// ---------------------------------------------------------------------------
// k1: 9-tap max along W then H of the RAW input (threshold deferred:
// maxpool(thresh(x)) == gate(maxpool(x)) since thresh preserves order and
// all raw values are >= 0). One block = full W row (128 threads x float4).
// No smem, no syncthreads. H-ring uses hh%9 under unroll-9 => renaming only.
// ---------------------------------------------------------------------------
__global__ void __launch_bounds__(128) k_wh(const float4* __restrict__ in) {
    const int t  = threadIdx.x;           // float4 index in row, 0..127
    const int h0 = blockIdx.y * TH1;
    const int d  = blockIdx.z;
    const float4* base = in    + (size_t)d * HH * W4;
    float4*       tmpb = g_tmp + (size_t)d * HH * W4;

    const float4 z4 = make_float4(0.f, 0.f, 0.f, 0.f);
    float4 ring[9];

#pragma unroll 9
    for (int hh = 0; hh < TH1 + 8; hh++) {   // 72 trips (multiple of 9)
        const int hi = h0 - 4 + hh;
        const bool rowok = (hi >= 0) & (hi < HH);
        const float4* row = base + (size_t)hi * W4;

        float4 L = (rowok && t > 0)       ? row[t - 1] : z4;
        float4 M = rowok                  ? row[t]     : z4;
        float4 R = (rowok && t < W4 - 1)  ? row[t + 1] : z4;

        // a0..a11 = L.xyzw M.xyzw R.xyzw ; output i = max(a[i..i+8])
        float c = fmaxf(fmaxf(fmaxf(L.w, M.x), fmaxf(M.y, M.z)),
                        fmaxf(M.w, R.x));                  // max(a3..a8)
        float4 y;
        y.x = fmaxf(fmaxf(c, L.x), fmaxf(L.y, L.z));
        y.y = fmaxf(fmaxf(c, L.y), fmaxf(L.z, R.y));
        y.z = fmaxf(fmaxf(c, L.z), fmaxf(R.y, R.z));
        y.w = fmaxf(fmaxf(c, R.y), fmaxf(R.z, R.w));

        ring[hh % 9] = y;                 // static index per unrolled slot

        if (hh >= 8) {                    // all 9 slots valid from here
            float4 m = ring[0];
#pragma unroll
            for (int i = 1; i < 9; i++) {
                m.x = fmaxf(m.x, ring[i].x);
                m.y = fmaxf(m.y, ring[i].y);
                m.z = fmaxf(m.z, ring[i].z);
                m.w = fmaxf(m.w, ring[i].w);
            }
            const int ho = h0 + hh - 8;
            tmpb[(size_t)ho * W4 + t] = m;
        }
    }
}

// ---------------------------------------------------------------------------
// k2: 9-tap max along D (register ring, float4) + threshold/strict-max gate.
// Ring MUST be zero-initialized: the zero slots serve as the d=-4..-1 padding
// for the first 4 output planes (first store happens after only 5 writes).
// ---------------------------------------------------------------------------
__global__ void __launch_bounds__(128) k_d(const float4* __restrict__ in,
                                           float4* __restrict__ out) {
    const size_t col   = (size_t)blockIdx.x * 128 + threadIdx.x;  // 0..65535
    const size_t slice = (size_t)HH * W4;

    const float4 z4 = make_float4(0.f, 0.f, 0.f, 0.f);
    float4 ring[9];
#pragma unroll
    for (int i = 0; i < 9; i++) ring[i] = z4;   // padding for d < 0

#pragma unroll 9
    for (int di = 0; di < 72; di++) {     // 72 trips (multiple of 9)
        float4 v = z4;
        if (di < DD) v = g_tmp[(size_t)di * slice + col];
        ring[di % 9] = v;

        const int dd = di - 4;
        if (dd >= 0 && dd < DD) {
            float4 m = ring[0];
#pragma unroll
            for (int i = 1; i < 9; i++) {
                m.x = fmaxf(m.x, ring[i].x);
                m.y = fmaxf(m.y, ring[i].y);
                m.z = fmaxf(m.z, ring[i].z);
                m.w = fmaxf(m.w, ring[i].w);
            }
            const float4 x = in[(size_t)dd * slice + col];
            float4 o;
            o.x = (m.x > THRESH && m.x == x.x) ? m.x : 0.f;
            o.y = (m.y > THRESH && m.y == x.y) ? m.y : 0.f;
            o.z = (m.z > THRESH && m.z == x.z) ? m.z : 0.f;
            o.w = (m.w > THRESH && m.w == x.w) ? m.w : 0.f;
            out[(size_t)dd * slice + col] = o;
        }
    }
}

extern "C" void kernel_launch(void* const* d_in, const int* in_sizes, int n_in,
                              void* d_out, int out_size) {
    const float4* in  = (const float4*)d_in[0];
    float4*       out = (float4*)d_out;

    dim3 g1(1, HH / TH1, DD);            // (1, 8, 64) = 512 blocks
    k_wh<<<g1, 128>>>(in);

    dim3 g2((HH * W4) / 128);            // 512 blocks
    k_d<<<g2, 128>>>(in, out);
}

// round 4
// speedup vs baseline: 1.7573x; 1.4520x over previous
#include <cuda_runtime.h>

#define DD 64
#define HH 512
#define WW 512
#define W4 (WW / 4)
#define THRESH 0.5f

// 64 MB scratch (device global per allocation-free rule): W+H pooled volume
__device__ float4 g_tmp[(size_t)DD * HH * W4];

#define TH1 19   // H rows produced per block in k1 -> trips = 27 (multiple of 9)
#define GY1 27   // ceil(512/19) = 27 (covers 513, last block guarded)

#define DSEG 16  // D outputs per thread in k2 -> 24 loads incl. halo

// ---------------------------------------------------------------------------
// k1: 9-tap max along W then H of the RAW input (threshold deferred:
// maxpool(thresh(x)) == gate(maxpool(x)) since thresh preserves order and
// all raw values are >= 0; 0-padding is exact). One block = full W row
// (128 threads x float4) x TH1 H-rows. No smem/syncs; mod-9 register ring.
// ---------------------------------------------------------------------------
__global__ void __launch_bounds__(128) k_wh(const float4* __restrict__ in) {
    const int t  = threadIdx.x;           // float4 index in row, 0..127
    const int h0 = blockIdx.y * TH1;
    const int d  = blockIdx.z;
    const float4* base = in    + (size_t)d * HH * W4;
    float4*       tmpb = g_tmp + (size_t)d * HH * W4;

    const float4 z4 = make_float4(0.f, 0.f, 0.f, 0.f);
    float4 ring[9];

#pragma unroll 9
    for (int hh = 0; hh < TH1 + 8; hh++) {   // 27 trips (multiple of 9)
        const int hi = h0 - 4 + hh;
        const bool rowok = (hi >= 0) & (hi < HH);
        const float4* row = base + (size_t)hi * W4;

        float4 L = (rowok && t > 0)       ? row[t - 1] : z4;
        float4 M = rowok                  ? row[t]     : z4;
        float4 R = (rowok && t < W4 - 1)  ? row[t + 1] : z4;

        // a0..a11 = L.xyzw M.xyzw R.xyzw ; output i = max(a[i..i+8])
        float c = fmaxf(fmaxf(fmaxf(L.w, M.x), fmaxf(M.y, M.z)),
                        fmaxf(M.w, R.x));                  // max(a3..a8)
        float4 y;
        y.x = fmaxf(fmaxf(c, L.x), fmaxf(L.y, L.z));
        y.y = fmaxf(fmaxf(c, L.y), fmaxf(L.z, R.y));
        y.z = fmaxf(fmaxf(c, L.z), fmaxf(R.y, R.z));
        y.w = fmaxf(fmaxf(c, R.y), fmaxf(R.z, R.w));

        ring[hh % 9] = y;                 // static index per unrolled slot

        const int ho = h0 + hh - 8;       // output row lags cursor by 4 (=hh-8)
        if (hh >= 8 && ho < HH) {
            float4 m = ring[0];
#pragma unroll
            for (int i = 1; i < 9; i++) {
                m.x = fmaxf(m.x, ring[i].x);
                m.y = fmaxf(m.y, ring[i].y);
                m.z = fmaxf(m.z, ring[i].z);
                m.w = fmaxf(m.w, ring[i].w);
            }
            tmpb[(size_t)ho * W4 + t] = m;
        }
    }
}

// ---------------------------------------------------------------------------
// k2: 9-tap max along D (zero-init register ring, float4) + threshold /
// strict-local-max gate. D split into 4 segments of DSEG outputs per thread
// (24 loads incl. +-4 halo) for 4x occupancy. Fully unrolled -> static ring
// indices. Zero ring slots double as out-of-range D padding.
// grid: (HH*W4/128, DD/DSEG), block 128.
// ---------------------------------------------------------------------------
__global__ void __launch_bounds__(128) k_d(const float4* __restrict__ in,
                                           float4* __restrict__ out) {
    const size_t col   = (size_t)blockIdx.x * 128 + threadIdx.x;  // 0..65535
    const int    d0    = blockIdx.y * DSEG;
    const size_t slice = (size_t)HH * W4;

    const float4 z4 = make_float4(0.f, 0.f, 0.f, 0.f);
    float4 ring[9];
#pragma unroll
    for (int i = 0; i < 9; i++) ring[i] = z4;

#pragma unroll
    for (int di = 0; di < DSEG + 8; di++) {     // 24 trips, fully unrolled
        const int p = d0 + di - 4;              // plane being loaded
        float4 v = z4;
        if ((unsigned)p < DD) v = g_tmp[(size_t)p * slice + col];
        ring[di % 9] = v;

        const int o = di - 8;                   // output lags cursor by 4
        if (o >= 0) {                           // o in [0, DSEG)
            float4 m = ring[0];
#pragma unroll
            for (int i = 1; i < 9; i++) {
                m.x = fmaxf(m.x, ring[i].x);
                m.y = fmaxf(m.y, ring[i].y);
                m.z = fmaxf(m.z, ring[i].z);
                m.w = fmaxf(m.w, ring[i].w);
            }
            const size_t idx = (size_t)(d0 + o) * slice + col;
            const float4 x = in[idx];
            float4 ov;
            ov.x = (m.x > THRESH && m.x == x.x) ? m.x : 0.f;
            ov.y = (m.y > THRESH && m.y == x.y) ? m.y : 0.f;
            ov.z = (m.z > THRESH && m.z == x.z) ? m.z : 0.f;
            ov.w = (m.w > THRESH && m.w == x.w) ? m.w : 0.f;
            out[idx] = ov;
        }
    }
}

extern "C" void kernel_launch(void* const* d_in, const int* in_sizes, int n_in,
                              void* d_out, int out_size) {
    const float4* in  = (const float4*)d_in[0];
    float4*       out = (float4*)d_out;

    dim3 g1(1, GY1, DD);                 // (1, 27, 64) = 1728 blocks
    k_wh<<<g1, 128>>>(in);

    dim3 g2((HH * W4) / 128, DD / DSEG); // (512, 4) = 2048 blocks
    k_d<<<g2, 128>>>(in, out);
}